// round 2
// baseline (speedup 1.0000x reference)
#include <cuda_runtime.h>
#include <cstdint>

#define T_STEPS 2048
#define BATCH   32
#define HID     512
#define GATES   2048   // 4*H
#define DIN     512
#define NBLK    128
#define REC_THREADS 512
#define REC_SMEM_BYTES (120 * 1024)

// Scratch (device globals — no allocation allowed in kernel_launch).
__device__ __align__(16) float g_xp[(size_t)BATCH * T_STEPS * GATES]; // [b][t][4H]
__device__ __align__(16) float g_h[2 * BATCH * HID];                  // double-buffered h
__device__ unsigned g_arrive;
__device__ unsigned g_release;

// ---------------------------------------------------------------------------
// Kernel 1: x_proj GEMM   C[r][col] = sum_d X[r][d] * Wi[d][col]
//   M = 65536 (b*T+t), K = 512, N = 2048. Row-major everything.
//   128x128 block tile, 8x8 per-thread tile, K-chunk 16, f32x2 packed FMAs.
// ---------------------------------------------------------------------------
__global__ void __launch_bounds__(256) xproj_gemm(const float* __restrict__ X,
                                                  const float* __restrict__ Wi)
{
    __shared__ float As[16][128];   // As[k][r]
    __shared__ float Bs[16][128];   // Bs[k][c]
    const int tid = threadIdx.x;
    const int row0 = blockIdx.y * 128;
    const int col0 = blockIdx.x * 128;
    const int tx = tid & 15, ty = tid >> 4;

    unsigned long long acc2[8][4];
    #pragma unroll
    for (int i = 0; i < 8; i++)
        #pragma unroll
        for (int j = 0; j < 4; j++) acc2[i][j] = 0ull;   // (0.0f, 0.0f)

    for (int k0 = 0; k0 < DIN; k0 += 16) {
        #pragma unroll
        for (int i = 0; i < 2; i++) {
            int j = tid + i * 256;
            int r = j >> 2, kq = (j & 3) << 2;
            float4 v = *(const float4*)(X + (size_t)(row0 + r) * DIN + k0 + kq);
            As[kq + 0][r] = v.x; As[kq + 1][r] = v.y;
            As[kq + 2][r] = v.z; As[kq + 3][r] = v.w;
        }
        #pragma unroll
        for (int i = 0; i < 2; i++) {
            int j = tid + i * 256;
            int kk = j >> 5, c4 = (j & 31) << 2;
            *(float4*)(&Bs[kk][c4]) =
                *(const float4*)(Wi + (size_t)(k0 + kk) * GATES + col0 + c4);
        }
        __syncthreads();
        #pragma unroll
        for (int kk = 0; kk < 16; kk++) {
            float a[8];
            *(float4*)&a[0] = *(const float4*)&As[kk][ty * 8];
            *(float4*)&a[4] = *(const float4*)&As[kk][ty * 8 + 4];
            ulonglong2 b01 = *(const ulonglong2*)&Bs[kk][tx * 8];
            ulonglong2 b23 = *(const ulonglong2*)&Bs[kk][tx * 8 + 4];
            #pragma unroll
            for (int i = 0; i < 8; i++) {
                unsigned long long aa;
                asm("mov.b64 %0, {%1, %1};" : "=l"(aa) : "f"(a[i]));
                asm("fma.rn.f32x2 %0, %1, %2, %0;" : "+l"(acc2[i][0]) : "l"(aa), "l"(b01.x));
                asm("fma.rn.f32x2 %0, %1, %2, %0;" : "+l"(acc2[i][1]) : "l"(aa), "l"(b01.y));
                asm("fma.rn.f32x2 %0, %1, %2, %0;" : "+l"(acc2[i][2]) : "l"(aa), "l"(b23.x));
                asm("fma.rn.f32x2 %0, %1, %2, %0;" : "+l"(acc2[i][3]) : "l"(aa), "l"(b23.y));
            }
        }
        __syncthreads();
    }
    #pragma unroll
    for (int i = 0; i < 8; i++) {
        size_t r = (size_t)row0 + ty * 8 + i;
        float o[8];
        #pragma unroll
        for (int j = 0; j < 4; j++)
            asm("mov.b64 {%0, %1}, %2;" : "=f"(o[2*j]), "=f"(o[2*j+1]) : "l"(acc2[i][j]));
        *(float4*)(g_xp + r * GATES + col0 + tx * 8)     = *(float4*)&o[0];
        *(float4*)(g_xp + r * GATES + col0 + tx * 8 + 4) = *(float4*)&o[4];
    }
}

// ---------------------------------------------------------------------------
// Init: barrier state + h0 -> g_h buffer 0
// ---------------------------------------------------------------------------
__global__ void init_kernel(const float* __restrict__ h0)
{
    int i = blockIdx.x * blockDim.x + threadIdx.x;
    if (i == 0) { g_arrive = 0; *(volatile unsigned*)&g_release = 0u; }
    if (i < BATCH * HID) g_h[i] = h0[i];
}

// ---------------------------------------------------------------------------
// Kernel 2: persistent LSTM recurrence.
//   128 blocks x 512 threads (16 warps). Block bi owns h-cols [4bi,4bi+4) and
//   the 16 z-cols {4bi+m + 512q}. Warp w=(q*4+m) computes one z-col for all 32
//   batches (lane = batch). Wh tile cached in smem once; h staged per step
//   into XOR-swizzled smem; c state in registers of warps 0-3.
// ---------------------------------------------------------------------------
__device__ __forceinline__ float fast_sigmoid(float x) {
    return __fdividef(1.0f, 1.0f + __expf(-x));
}
__device__ __forceinline__ float fast_tanh(float x) {
    return __fdividef(2.0f, 1.0f + __expf(-2.0f * x)) - 1.0f;
}

__global__ void __launch_bounds__(REC_THREADS) lstm_recurrent(
    const float* __restrict__ c0,
    const float* __restrict__ Wh,
    const float* __restrict__ bias,
    float* __restrict__ out)
{
    extern __shared__ float smem[];
    float* whs = smem;                       // [16][512]
    float* hs  = smem + 16 * HID;            // [32][512] swizzled (float4 chunks)
    float* zs  = smem + 16 * HID + 32 * HID; // [16][32]

    const int tid = threadIdx.x;
    const int w = tid >> 5;
    const int b = tid & 31;
    const int bi = blockIdx.x;
    const int q = w >> 2, m = w & 3;
    const int col  = q * HID + bi * 4 + m;   // z column this warp computes
    const int hcol = bi * 4 + m;             // h column (warps 0-3 only)

    // One-time: Wh column -> smem (whs[w][k] = Wh[k][col])
    #pragma unroll 4
    for (int k = b; k < HID; k += 32)
        whs[w * HID + k] = Wh[(size_t)k * GATES + col];
    const float biasv = bias[col];
    float c_st = (w < 4) ? c0[b * HID + hcol] : 0.0f;

    const int sw = b & 7;
    const ulonglong2* hp[8];
    #pragma unroll
    for (int u = 0; u < 8; u++)
        hp[u] = (const ulonglong2*)hs + b * 128 + (u ^ sw);
    const ulonglong2* wp = (const ulonglong2*)whs + w * 128;

    // Stage h for step 0 (buffer 0 holds h0)
    {
        const float4* src = (const float4*)g_h;   // buffer 0
        #pragma unroll
        for (int i = 0; i < 8; i++) {
            int j = tid + i * REC_THREADS;        // float4 index, 4096 total
            int hb = j >> 7, k4 = j & 127;
            float4 v = __ldcg(src + j);
            ((float4*)hs)[hb * 128 + (k4 ^ (hb & 7))] = v;
        }
    }
    __syncthreads();

    // Prefetch x_proj for t=0
    float xpv = g_xp[((size_t)b * T_STEPS + 0) * GATES + col];

    for (int t = 0; t < T_STEPS; t++) {
        unsigned long long acc01, acc23;
        asm("mov.b64 %0, {%1, %2};" : "=l"(acc01) : "f"(xpv + biasv), "f"(0.0f));
        acc23 = 0ull;
        #pragma unroll
        for (int j0 = 0; j0 < 128; j0 += 8) {
            #pragma unroll
            for (int u = 0; u < 8; u++) {
                // stored chunk j0+(u^sw) holds logical h chunk j0+u (XOR swizzle)
                ulonglong2 hv = hp[u][j0];
                ulonglong2 wv = wp[j0 + u];
                asm("fma.rn.f32x2 %0, %1, %2, %0;" : "+l"(acc01) : "l"(hv.x), "l"(wv.x));
                asm("fma.rn.f32x2 %0, %1, %2, %0;" : "+l"(acc23) : "l"(hv.y), "l"(wv.y));
            }
        }
        // Prefetch next step's x_proj (hides DRAM latency behind barrier+gates)
        if (t + 1 < T_STEPS)
            xpv = g_xp[((size_t)b * T_STEPS + (t + 1)) * GATES + col];

        float a0, a1, a2, a3;
        asm("mov.b64 {%0, %1}, %2;" : "=f"(a0), "=f"(a1) : "l"(acc01));
        asm("mov.b64 {%0, %1}, %2;" : "=f"(a2), "=f"(a3) : "l"(acc23));
        zs[w * 32 + b] = (a0 + a2) + (a1 + a3);
        __syncthreads();

        if (w < 4) {
            float zi = zs[(m     ) * 32 + b];
            float zf = zs[(4  + m) * 32 + b];
            float zg = zs[(8  + m) * 32 + b];
            float zo = zs[(12 + m) * 32 + b];
            float ig = fast_sigmoid(zi);
            float fg = fast_sigmoid(zf);
            float gg = fast_tanh(zg);
            float og = fast_sigmoid(zo);
            c_st = fg * c_st + ig * gg;
            float hnew = og * fast_tanh(c_st);
            g_h[(((t + 1) & 1) * BATCH * HID) + b * HID + hcol] = hnew;   // ping-pong
            out[((size_t)b * T_STEPS + t) * HID + hcol] = hnew;
            __threadfence();
        }
        __syncthreads();

        // Grid barrier (sense via monotonically increasing release value)
        if (tid == 0) {
            unsigned a = atomicAdd(&g_arrive, 1u);
            if (a == NBLK - 1) {
                g_arrive = 0;
                __threadfence();
                *(volatile unsigned*)&g_release = (unsigned)(t + 1);
            } else {
                while (*(volatile unsigned*)&g_release < (unsigned)(t + 1)) { }
            }
            __threadfence();
        }
        __syncthreads();

        // Stage h for step t+1 from the buffer just written (bypass stale L1)
        if (t + 1 < T_STEPS) {
            const float4* src = (const float4*)g_h + ((t + 1) & 1) * (BATCH * HID / 4);
            #pragma unroll
            for (int i = 0; i < 8; i++) {
                int j = tid + i * REC_THREADS;
                int hb = j >> 7, k4 = j & 127;
                float4 v = __ldcg(src + j);
                ((float4*)hs)[hb * 128 + (k4 ^ (hb & 7))] = v;
            }
            __syncthreads();
        }
    }
}

// ---------------------------------------------------------------------------
extern "C" void kernel_launch(void* const* d_in, const int* in_sizes, int n_in,
                              void* d_out, int out_size)
{
    const float* inputs = (const float*)d_in[0];   // [B,T,D]
    // d_in[1] = input_paddings (all valid, unused by reference path)
    const float* c0   = (const float*)d_in[2];     // [B,H]
    const float* h0   = (const float*)d_in[3];     // [B,H]
    const float* Wi   = (const float*)d_in[4];     // [D,4H]
    const float* Wh   = (const float*)d_in[5];     // [H,4H]
    const float* bias = (const float*)d_in[6];     // [4H]
    float* out = (float*)d_out;                    // [B,T,H]

    cudaFuncSetAttribute(lstm_recurrent,
                         cudaFuncAttributeMaxDynamicSharedMemorySize,
                         REC_SMEM_BYTES);

    xproj_gemm<<<dim3(GATES / 128, (BATCH * T_STEPS) / 128), 256>>>(inputs, Wi);
    init_kernel<<<(BATCH * HID + 255) / 256, 256>>>(h0);
    lstm_recurrent<<<NBLK, REC_THREADS, REC_SMEM_BYTES>>>(c0, Wh, bias, out);
}

// round 6
// speedup vs baseline: 1.5647x; 1.5647x over previous
#include <cuda_runtime.h>
#include <cstdint>

#define T_STEPS 2048
#define BATCH   32
#define HID     512
#define GATES   2048   // 4*H
#define DIN     512
#define NBLK    128
#define RTH     512
#define REC_SMEM_BYTES (128 * 1024)

// Scratch (device globals — no allocation allowed in kernel_launch).
__device__ __align__(16) float g_xp [(size_t)BATCH * T_STEPS * GATES]; // [b*T+t][col]
__device__ __align__(16) float g_xp2[(size_t)BATCH * GATES * T_STEPS]; // [b][col][t]
__device__ __align__(16) float g_h2 [2 * HID * BATCH];                 // [buf][k][b]
__device__ unsigned g_arrive;
__device__ unsigned g_release;

// ---------------------------------------------------------------------------
// Kernel 1: x_proj GEMM  (unchanged from R1 — known good)
// ---------------------------------------------------------------------------
__global__ void __launch_bounds__(256) xproj_gemm(const float* __restrict__ X,
                                                  const float* __restrict__ Wi)
{
    __shared__ float As[16][128];
    __shared__ float Bs[16][128];
    const int tid = threadIdx.x;
    const int row0 = blockIdx.y * 128;
    const int col0 = blockIdx.x * 128;
    const int tx = tid & 15, ty = tid >> 4;

    unsigned long long acc2[8][4];
    #pragma unroll
    for (int i = 0; i < 8; i++)
        #pragma unroll
        for (int j = 0; j < 4; j++) acc2[i][j] = 0ull;

    for (int k0 = 0; k0 < DIN; k0 += 16) {
        #pragma unroll
        for (int i = 0; i < 2; i++) {
            int j = tid + i * 256;
            int r = j >> 2, kq = (j & 3) << 2;
            float4 v = *(const float4*)(X + (size_t)(row0 + r) * DIN + k0 + kq);
            As[kq + 0][r] = v.x; As[kq + 1][r] = v.y;
            As[kq + 2][r] = v.z; As[kq + 3][r] = v.w;
        }
        #pragma unroll
        for (int i = 0; i < 2; i++) {
            int j = tid + i * 256;
            int kk = j >> 5, c4 = (j & 31) << 2;
            *(float4*)(&Bs[kk][c4]) =
                *(const float4*)(Wi + (size_t)(k0 + kk) * GATES + col0 + c4);
        }
        __syncthreads();
        #pragma unroll
        for (int kk = 0; kk < 16; kk++) {
            float a[8];
            *(float4*)&a[0] = *(const float4*)&As[kk][ty * 8];
            *(float4*)&a[4] = *(const float4*)&As[kk][ty * 8 + 4];
            ulonglong2 b01 = *(const ulonglong2*)&Bs[kk][tx * 8];
            ulonglong2 b23 = *(const ulonglong2*)&Bs[kk][tx * 8 + 4];
            #pragma unroll
            for (int i = 0; i < 8; i++) {
                unsigned long long aa;
                asm("mov.b64 %0, {%1, %1};" : "=l"(aa) : "f"(a[i]));
                asm("fma.rn.f32x2 %0, %1, %2, %0;" : "+l"(acc2[i][0]) : "l"(aa), "l"(b01.x));
                asm("fma.rn.f32x2 %0, %1, %2, %0;" : "+l"(acc2[i][1]) : "l"(aa), "l"(b01.y));
                asm("fma.rn.f32x2 %0, %1, %2, %0;" : "+l"(acc2[i][2]) : "l"(aa), "l"(b23.x));
                asm("fma.rn.f32x2 %0, %1, %2, %0;" : "+l"(acc2[i][3]) : "l"(aa), "l"(b23.y));
            }
        }
        __syncthreads();
    }
    #pragma unroll
    for (int i = 0; i < 8; i++) {
        size_t r = (size_t)row0 + ty * 8 + i;
        float o[8];
        #pragma unroll
        for (int j = 0; j < 4; j++)
            asm("mov.b64 {%0, %1}, %2;" : "=f"(o[2*j]), "=f"(o[2*j+1]) : "l"(acc2[i][j]));
        *(float4*)(g_xp + r * GATES + col0 + tx * 8)     = *(float4*)&o[0];
        *(float4*)(g_xp + r * GATES + col0 + tx * 8 + 4) = *(float4*)&o[4];
    }
}

// ---------------------------------------------------------------------------
// Kernel 1b: transpose x_proj [b*T+t][col] -> [b][col][t]
// ---------------------------------------------------------------------------
__global__ void __launch_bounds__(256) xp_transpose()
{
    __shared__ float tile[32][33];
    const int tx = threadIdx.x & 31, ty = threadIdx.x >> 5;  // ty 0..7
    const size_t r0 = (size_t)blockIdx.y * 32;               // row = b*T + t
    const int c0 = blockIdx.x * 32;
    #pragma unroll
    for (int i = 0; i < 4; i++)
        tile[ty + i * 8][tx] = g_xp[(r0 + ty + i * 8) * GATES + c0 + tx];
    __syncthreads();
    const int bb = (int)(r0 >> 11);
    const int t0 = (int)(r0 & 2047);
    #pragma unroll
    for (int i = 0; i < 4; i++)
        g_xp2[((size_t)bb * GATES + c0 + ty + i * 8) * T_STEPS + t0 + tx] =
            tile[tx][ty + i * 8];
}

// ---------------------------------------------------------------------------
// Init: barrier state + h0 -> g_h2 buffer 0 in [k][b] layout
// ---------------------------------------------------------------------------
__global__ void init_kernel(const float* __restrict__ h0)
{
    int i = blockIdx.x * blockDim.x + threadIdx.x;
    if (i == 0) { g_arrive = 0; g_release = 0; }
    if (i < HID * BATCH) {
        int k = i >> 5, b = i & 31;
        g_h2[i] = h0[b * HID + k];
    }
}

// ---------------------------------------------------------------------------
// Kernel 2: persistent LSTM recurrence, restructured.
//   128 blocks x 512 threads (16 warps). Block bi owns h-cols [4bi,4bi+4) and
//   z-cols {q*512 + 4bi + m}. Warp w computes ALL 16 local cols over K-chunk
//   [32w, 32w+32): lane = batch. h slice staged privately per warp (coalesced
//   from k-major g_h2); w columns broadcast from smem; 16-way reduction via
//   smem; gates on warps 0-3; release/acquire grid barrier once per step.
// ---------------------------------------------------------------------------
__device__ __forceinline__ float fast_sigmoid(float x) {
    return __fdividef(1.0f, 1.0f + __expf(-x));
}
__device__ __forceinline__ float fast_tanh(float x) {
    return __fdividef(2.0f, 1.0f + __expf(-2.0f * x)) - 1.0f;
}

__global__ void __launch_bounds__(RTH) lstm_recurrent(
    const float* __restrict__ c0,
    const float* __restrict__ Wh,
    const float* __restrict__ bias,
    float* __restrict__ out)
{
    extern __shared__ float sm[];
    float* hsw = sm;                   // 16 warps x [32 k][32 b]       = 16384 f
    float* wsm = sm + 16384;           // [128 jg][16 c][4 ksub]        =  8192 f
    float* red = sm + 16384 + 8192;    // [16 c][16 w][32 b]            =  8192 f

    const int tid = threadIdx.x;
    const int w   = tid >> 5;
    const int b   = tid & 31;
    const int bi  = blockIdx.x;

    // One-time: fill wsm. wsm[jg][c][ks] = Wh[(4jg+ks)][colglobal(c)],
    // colglobal(c) = (c>>2)*512 + bi*4 + (c&3)
    #pragma unroll
    for (int i = 0; i < 16; i++) {
        int idx = tid + i * RTH;
        int jg = idx >> 6, rem = idx & 63, c = rem >> 2, ks = rem & 3;
        int col = (c >> 2) * HID + bi * 4 + (c & 3);
        wsm[idx] = Wh[(size_t)(jg * 4 + ks) * GATES + col];
    }

    // Gate-thread state (warps 0-3): m = w, hcol = 4bi + m
    const int hcol = bi * 4 + w;
    float bq[4];
    const float* xq[4];
    float c_st = 0.0f;
    if (w < 4) {
        #pragma unroll
        for (int q = 0; q < 4; q++) {
            bq[q] = bias[q * HID + hcol];
            xq[q] = g_xp2 + ((size_t)b * GATES + q * HID + hcol) * T_STEPS;
        }
        c_st = c0[b * HID + hcol];
    }
    __syncthreads();

    float* hsw_w = hsw + w * 1024;                       // this warp's h slice
    const ulonglong2* wsm_w = (const ulonglong2*)wsm + w * 8 * 16;

    float4 xv[4];
    #pragma unroll 4
    for (int t = 0; t < T_STEPS; t++) {
        // Prefetch x_proj for 4 steps (gate threads only); folds under unroll-4.
        if (w < 4 && (t & 3) == 0) {
            #pragma unroll
            for (int q = 0; q < 4; q++) xv[q] = *(const float4*)(xq[q] + t);
        }

        // Stage own 4KB h slice: coalesced LDG.128 (L2, bypass stale L1) -> STS.128
        {
            const float4* src = (const float4*)(g_h2 + (t & 1) * (HID * BATCH)) + w * 256;
            float4 hv[8];
            #pragma unroll
            for (int i = 0; i < 8; i++) hv[i] = __ldcg(src + b + i * 32);
            float4* dst = (float4*)hsw_w;
            #pragma unroll
            for (int i = 0; i < 8; i++) dst[b + i * 32] = hv[i];
            __syncwarp();
        }

        // Partial z for 16 cols over this warp's 32-k chunk
        unsigned long long acc[16];
        #pragma unroll
        for (int c = 0; c < 16; c++) acc[c] = 0ull;
        #pragma unroll
        for (int kq = 0; kq < 8; kq++) {
            float h0 = hsw_w[(kq * 4 + 0) * 32 + b];
            float h1 = hsw_w[(kq * 4 + 1) * 32 + b];
            float h2 = hsw_w[(kq * 4 + 2) * 32 + b];
            float h3 = hsw_w[(kq * 4 + 3) * 32 + b];
            unsigned long long X01, X23;
            asm("mov.b64 %0, {%1, %2};" : "=l"(X01) : "f"(h0), "f"(h1));
            asm("mov.b64 %0, {%1, %2};" : "=l"(X23) : "f"(h2), "f"(h3));
            const ulonglong2* wq = wsm_w + kq * 16;
            #pragma unroll
            for (int c = 0; c < 16; c++) {
                ulonglong2 wv = wq[c];   // broadcast LDS.128
                asm("fma.rn.f32x2 %0, %1, %2, %0;" : "+l"(acc[c]) : "l"(X01), "l"(wv.x));
                asm("fma.rn.f32x2 %0, %1, %2, %0;" : "+l"(acc[c]) : "l"(X23), "l"(wv.y));
            }
        }
        // Finalize pairs, write partials: red[c][w][b]
        #pragma unroll
        for (int c = 0; c < 16; c++) {
            float lo, hi;
            asm("mov.b64 {%0, %1}, %2;" : "=f"(lo), "=f"(hi) : "l"(acc[c]));
            red[(c * 16 + w) * 32 + b] = lo + hi;
        }
        __syncthreads();

        // Gates: warps 0-3, thread = (m=w, batch=b). Sum 16 partials per gate col.
        if (w < 4) {
            float z[4];
            #pragma unroll
            for (int q = 0; q < 4; q++) {
                const float* rp = red + ((q * 4 + w) * 16) * 32 + b;
                float s0 = 0.f, s1 = 0.f, s2 = 0.f, s3 = 0.f;
                #pragma unroll
                for (int wk = 0; wk < 16; wk += 4) {
                    s0 += rp[(wk + 0) * 32];
                    s1 += rp[(wk + 1) * 32];
                    s2 += rp[(wk + 2) * 32];
                    s3 += rp[(wk + 3) * 32];
                }
                float xc = (t & 3) == 0 ? xv[q].x :
                           (t & 3) == 1 ? xv[q].y :
                           (t & 3) == 2 ? xv[q].z : xv[q].w;
                z[q] = ((s0 + s1) + (s2 + s3)) + xc + bq[q];
            }
            float ig = fast_sigmoid(z[0]);
            float fg = fast_sigmoid(z[1]);
            float gg = fast_tanh(z[2]);
            float og = fast_sigmoid(z[3]);
            c_st = fg * c_st + ig * gg;
            float hn = og * fast_tanh(c_st);
            g_h2[((t + 1) & 1) * (HID * BATCH) + hcol * 32 + b] = hn;
            out[(size_t)b * T_STEPS * HID + (size_t)t * HID + hcol] = hn;
        }
        __syncthreads();

        // Grid barrier: release/acquire (CG-style)
        if (tid == 0) {
            __threadfence();
            unsigned a = atomicAdd(&g_arrive, 1u);
            if (a == NBLK - 1) {
                g_arrive = 0;
                asm volatile("st.release.gpu.global.b32 [%0], %1;"
                             :: "l"(&g_release), "r"((unsigned)(t + 1)) : "memory");
            } else {
                unsigned r;
                do {
                    asm volatile("ld.acquire.gpu.global.b32 %0, [%1];"
                                 : "=r"(r) : "l"(&g_release) : "memory");
                } while (r < (unsigned)(t + 1));
            }
        }
        __syncthreads();
    }
}

// ---------------------------------------------------------------------------
extern "C" void kernel_launch(void* const* d_in, const int* in_sizes, int n_in,
                              void* d_out, int out_size)
{
    const float* inputs = (const float*)d_in[0];   // [B,T,D]
    // d_in[1] = input_paddings (all valid, unused)
    const float* c0   = (const float*)d_in[2];     // [B,H]
    const float* h0   = (const float*)d_in[3];     // [B,H]
    const float* Wi   = (const float*)d_in[4];     // [D,4H]
    const float* Wh   = (const float*)d_in[5];     // [H,4H]
    const float* bias = (const float*)d_in[6];     // [4H]
    float* out = (float*)d_out;                    // [B,T,H]

    cudaFuncSetAttribute(lstm_recurrent,
                         cudaFuncAttributeMaxDynamicSharedMemorySize,
                         REC_SMEM_BYTES);

    xproj_gemm<<<dim3(GATES / 128, (BATCH * T_STEPS) / 128), 256>>>(inputs, Wi);
    xp_transpose<<<dim3(GATES / 32, (BATCH * T_STEPS) / 32), 256>>>();
    init_kernel<<<(HID * BATCH + 255) / 256, 256>>>(h0);
    lstm_recurrent<<<NBLK, RTH, REC_SMEM_BYTES>>>(c0, Wh, bias, out);
}